// round 5
// baseline (speedup 1.0000x reference)
#include <cuda_runtime.h>
#include <math.h>
#include <stdint.h>

// Problem constants
#define BB 2
#define NN 2048
#define DD 1024
#define HH 16
#define DHD 64
#define QKVW (3 * HH * DHD)   // 3072

// Scratch buffers (device globals: allocation-free rule)
__device__ float g_qkv[BB * NN * QKVW];     // [B, N, 3072]  Q|K|V packed
__device__ float g_att[BB * NN * HH * DHD]; // [B, N, 1024]  attention output

// ============================================================================
// Helpers (sm_100 baseline ISA: mma.sync tf32 + cp.async; NO tcgen05/TMA)
// ============================================================================
__device__ __forceinline__ uint32_t smem_u32(const void* p) {
    uint32_t a;
    asm("{ .reg .u64 t; cvta.to.shared.u64 t, %1; cvt.u32.u64 %0, t; }"
        : "=r"(a) : "l"(p));
    return a;
}

__device__ __forceinline__ uint32_t f2tf(float x) {
    uint32_t r;
    asm("cvt.rna.tf32.f32 %0, %1;" : "=r"(r) : "f"(x));
    return r;
}

__device__ __forceinline__ void cp_async16(uint32_t saddr, const void* gptr) {
    asm volatile("cp.async.cg.shared.global [%0], [%1], 16;"
                 :: "r"(saddr), "l"(gptr));
}
#define CP_COMMIT() asm volatile("cp.async.commit_group;" ::: "memory")
#define CP_WAIT(n)  asm volatile("cp.async.wait_group %0;" :: "n"(n) : "memory")

// D += A(16x8, tf32, row) * B(8x8, tf32, col)
__device__ __forceinline__ void mma16n8k8(float* d, const uint32_t* a, const uint32_t* b) {
    asm volatile(
        "mma.sync.aligned.m16n8k8.row.col.f32.tf32.tf32.f32 "
        "{%0,%1,%2,%3}, {%4,%5,%6,%7}, {%8,%9}, {%0,%1,%2,%3};"
        : "+f"(d[0]), "+f"(d[1]), "+f"(d[2]), "+f"(d[3])
        : "r"(a[0]), "r"(a[1]), "r"(a[2]), "r"(a[3]), "r"(b[0]), "r"(b[1]));
}

// ============================================================================
// tf32 mma.sync GEMM (NT): C[m,n] = sum_k A[m,k] * W[n,k] + bias[n]
// CTA tile 128x128, BK=32, 256 threads (8 warps, 2x4), warp tile 64x32.
// SMEM: [row][k] at pitch 36 floats (conflict-free fragment LDS), double-buffered.
// ============================================================================
#define PITCH 36
#define BUF_FLOATS (128 * PITCH)                 // 4608 floats per matrix buffer
#define GM_SMEM_BYTES (4 * BUF_FLOATS * 4)       // A0,B0,A1,B1 = 73728 B

__global__ __launch_bounds__(256, 2)
void gemm_mma_tf32(const float* __restrict__ A,
                   const float* __restrict__ W,
                   const float* __restrict__ bias,
                   float* __restrict__ C,
                   int M, int Nc, int K)
{
    extern __shared__ float sm[];
    float* const Abuf[2] = { sm,                 sm + 2 * BUF_FLOATS };
    float* const Bbuf[2] = { sm + BUF_FLOATS,    sm + 3 * BUF_FLOATS };

    const int tid = threadIdx.x;
    const int wid = tid >> 5;
    const int lane = tid & 31;
    const int wm = wid & 1;          // 0..1 -> 64-row half
    const int wn = wid >> 1;         // 0..3 -> 32-col quarter
    const int g  = lane >> 2;        // groupID 0..7
    const int tg = lane & 3;         // thread-in-group 0..3
    const int m0 = blockIdx.y * 128;
    const int n0 = blockIdx.x * 128;

    const int r_cp  = tid >> 3;          // 0..31 base row for copies
    const int c4_cp = (tid & 7) * 4;     // 0,4,...,28

    float d[4][4][4];
#pragma unroll
    for (int i = 0; i < 4; ++i)
#pragma unroll
        for (int j = 0; j < 4; ++j)
#pragma unroll
            for (int r = 0; r < 4; ++r) d[i][j][r] = 0.f;

    const int nch = K >> 5;   // chunks of 32

    // --- issue copy of chunk kc into buffer buf ---
    auto issue_copy = [&](int buf, int kc) {
        const float* Ag = A + (size_t)m0 * K + kc * 32;
        const float* Wg = W + (size_t)n0 * K + kc * 32;
        float* as = Abuf[buf];
        float* bs = Bbuf[buf];
#pragma unroll
        for (int s = 0; s < 4; ++s) {
            int r = r_cp + s * 32;
            cp_async16(smem_u32(as + r * PITCH + c4_cp), Ag + (size_t)r * K + c4_cp);
            cp_async16(smem_u32(bs + r * PITCH + c4_cp), Wg + (size_t)r * K + c4_cp);
        }
        CP_COMMIT();
    };

    issue_copy(0, 0);

    for (int kc = 0; kc < nch; ++kc) {
        const int buf = kc & 1;
        if (kc + 1 < nch) {
            issue_copy(buf ^ 1, kc + 1);
            CP_WAIT(1);
        } else {
            CP_WAIT(0);
        }
        __syncthreads();

        const float* as = Abuf[buf];
        const float* bs = Bbuf[buf];

#pragma unroll
        for (int ks = 0; ks < 4; ++ks) {
            const int kb = ks * 8;
            uint32_t afr[4][4], bfr[4][2];
#pragma unroll
            for (int i = 0; i < 4; ++i) {
                const float* ap = as + (wm * 64 + i * 16 + g) * PITCH + kb + tg;
                afr[i][0] = f2tf(ap[0]);
                afr[i][1] = f2tf(ap[8 * PITCH]);
                afr[i][2] = f2tf(ap[4]);
                afr[i][3] = f2tf(ap[8 * PITCH + 4]);
            }
#pragma unroll
            for (int j = 0; j < 4; ++j) {
                const float* bp = bs + (wn * 32 + j * 8 + g) * PITCH + kb + tg;
                bfr[j][0] = f2tf(bp[0]);
                bfr[j][1] = f2tf(bp[4]);
            }
#pragma unroll
            for (int i = 0; i < 4; ++i)
#pragma unroll
                for (int j = 0; j < 4; ++j)
                    mma16n8k8(d[i][j], afr[i], bfr[j]);
        }
        __syncthreads();
    }

    // Epilogue: bias + store (float2 per fragment row)
#pragma unroll
    for (int j = 0; j < 4; ++j) {
        const int ncol = n0 + wn * 32 + j * 8 + 2 * tg;
        const float bv0 = bias[ncol];
        const float bv1 = bias[ncol + 1];
#pragma unroll
        for (int i = 0; i < 4; ++i) {
            const int mrow = m0 + wm * 64 + i * 16 + g;
            float2 v0 = { d[i][j][0] + bv0, d[i][j][1] + bv1 };
            float2 v1 = { d[i][j][2] + bv0, d[i][j][3] + bv1 };
            *(float2*)(C + (size_t)mrow * Nc + ncol) = v0;
            *(float2*)(C + (size_t)(mrow + 8) * Nc + ncol) = v1;
        }
    }
}

// ----------------------------------------------------------------------------
// Flash-style attention (fp32) — unchanged (passed R1).
// ----------------------------------------------------------------------------
#define ATT_PITCH 65
#define ATT_SMEM_FLOATS (3 * 64 * ATT_PITCH + 3 * 64)

__global__ __launch_bounds__(256)
void attn_kernel(const float* __restrict__ qkv, float* __restrict__ out)
{
    extern __shared__ float sma[];
    float* Qs   = sma;
    float* Ks   = Qs + 64 * ATT_PITCH;
    float* Vs   = Ks + 64 * ATT_PITCH;
    float* mrow = Vs + 64 * ATT_PITCH;
    float* lrow = mrow + 64;
    float* arow = lrow + 64;

    const int tid = threadIdx.x;
    const int tx = tid & 15;
    const int ty = tid >> 4;
    const int bh = blockIdx.y;
    const int b = bh >> 4;
    const int h = bh & 15;
    const int q0 = blockIdx.x * 64;

    const size_t rs = QKVW;
    const float* Qg = qkv + (size_t)(b * NN + q0) * rs + h * DHD;
    const float* Kg = qkv + (size_t)(b * NN) * rs + HH * DHD + h * DHD;
    const float* Vg = qkv + (size_t)(b * NN) * rs + 2 * HH * DHD + h * DHD;
    const float scale = 0.125f;

#pragma unroll
    for (int s = 0; s < 4; ++s) {
        int i = tid + s * 256;
        int r = i >> 4;
        int c = (i & 15) * 4;
        float4 v = *(const float4*)(Qg + (size_t)r * rs + c);
        Qs[r * ATT_PITCH + c + 0] = v.x * scale;
        Qs[r * ATT_PITCH + c + 1] = v.y * scale;
        Qs[r * ATT_PITCH + c + 2] = v.z * scale;
        Qs[r * ATT_PITCH + c + 3] = v.w * scale;
    }
    if (tid < 64) { mrow[tid] = -INFINITY; lrow[tid] = 0.f; }

    float Oacc[4][4];
#pragma unroll
    for (int i = 0; i < 4; ++i)
#pragma unroll
        for (int j = 0; j < 4; ++j) Oacc[i][j] = 0.f;

    __syncthreads();

    for (int j0 = 0; j0 < NN; j0 += 64) {
#pragma unroll
        for (int s = 0; s < 4; ++s) {
            int i = tid + s * 256;
            int r = i >> 4;
            int c = (i & 15) * 4;
            float4 kv = *(const float4*)(Kg + (size_t)(j0 + r) * rs + c);
            Ks[r * ATT_PITCH + c + 0] = kv.x;
            Ks[r * ATT_PITCH + c + 1] = kv.y;
            Ks[r * ATT_PITCH + c + 2] = kv.z;
            Ks[r * ATT_PITCH + c + 3] = kv.w;
            float4 vv = *(const float4*)(Vg + (size_t)(j0 + r) * rs + c);
            Vs[r * ATT_PITCH + c + 0] = vv.x;
            Vs[r * ATT_PITCH + c + 1] = vv.y;
            Vs[r * ATT_PITCH + c + 2] = vv.z;
            Vs[r * ATT_PITCH + c + 3] = vv.w;
        }
        __syncthreads();

        float Sa[4][4];
#pragma unroll
        for (int i = 0; i < 4; ++i)
#pragma unroll
            for (int j = 0; j < 4; ++j) Sa[i][j] = 0.f;

#pragma unroll
        for (int dd = 0; dd < 64; ++dd) {
            float qf[4], kf[4];
#pragma unroll
            for (int i = 0; i < 4; ++i) qf[i] = Qs[(ty * 4 + i) * ATT_PITCH + dd];
#pragma unroll
            for (int j = 0; j < 4; ++j) kf[j] = Ks[(tx * 4 + j) * ATT_PITCH + dd];
#pragma unroll
            for (int i = 0; i < 4; ++i)
#pragma unroll
                for (int j = 0; j < 4; ++j)
                    Sa[i][j] += qf[i] * kf[j];
        }
        __syncthreads();

#pragma unroll
        for (int i = 0; i < 4; ++i)
#pragma unroll
            for (int j = 0; j < 4; ++j)
                Ks[(ty * 4 + i) * ATT_PITCH + tx * 4 + j] = Sa[i][j];
        __syncthreads();

        {
            const int r = tid >> 2;
            const int seg = (tid & 3) * 16;
            float* Srow = Ks + r * ATT_PITCH + seg;
            float mx = -INFINITY;
#pragma unroll
            for (int j = 0; j < 16; ++j) mx = fmaxf(mx, Srow[j]);
            mx = fmaxf(mx, __shfl_xor_sync(0xffffffffu, mx, 1));
            mx = fmaxf(mx, __shfl_xor_sync(0xffffffffu, mx, 2));
            float mold = mrow[r];
            float mnew = fmaxf(mold, mx);
            float sum = 0.f;
#pragma unroll
            for (int j = 0; j < 16; ++j) {
                float e = __expf(Srow[j] - mnew);
                Srow[j] = e;
                sum += e;
            }
            sum += __shfl_xor_sync(0xffffffffu, sum, 1);
            sum += __shfl_xor_sync(0xffffffffu, sum, 2);
            if ((tid & 3) == 0) {
                float al = __expf(mold - mnew);
                arow[r] = al;
                lrow[r] = lrow[r] * al + sum;
                mrow[r] = mnew;
            }
        }
        __syncthreads();

        float al[4];
#pragma unroll
        for (int i = 0; i < 4; ++i) al[i] = arow[ty * 4 + i];
#pragma unroll
        for (int i = 0; i < 4; ++i)
#pragma unroll
            for (int j = 0; j < 4; ++j) Oacc[i][j] *= al[i];

#pragma unroll
        for (int k = 0; k < 64; ++k) {
            float pf[4], vf[4];
#pragma unroll
            for (int i = 0; i < 4; ++i) pf[i] = Ks[(ty * 4 + i) * ATT_PITCH + k];
#pragma unroll
            for (int j = 0; j < 4; ++j) vf[j] = Vs[k * ATT_PITCH + tx * 4 + j];
#pragma unroll
            for (int i = 0; i < 4; ++i)
#pragma unroll
                for (int j = 0; j < 4; ++j)
                    Oacc[i][j] += pf[i] * vf[j];
        }
        __syncthreads();
    }

#pragma unroll
    for (int i = 0; i < 4; ++i) {
        float inv = 1.f / lrow[ty * 4 + i];
        float4 o;
        o.x = Oacc[i][0] * inv;
        o.y = Oacc[i][1] * inv;
        o.z = Oacc[i][2] * inv;
        o.w = Oacc[i][3] * inv;
        float* op = out + (size_t)(b * NN + q0 + ty * 4 + i) * (HH * DHD)
                        + h * DHD + tx * 4;
        *(float4*)op = o;
    }
}

// ----------------------------------------------------------------------------
// Launch
// ----------------------------------------------------------------------------
extern "C" void kernel_launch(void* const* d_in, const int* in_sizes, int n_in,
                              void* d_out, int out_size)
{
    const float* x     = (const float*)d_in[0];
    const float* W_w   = (const float*)d_in[1];
    const float* W_b   = (const float*)d_in[2];
    const float* out_w = (const float*)d_in[3];
    const float* out_b = (const float*)d_in[4];
    float* out = (float*)d_out;

    float* qkv = nullptr;
    float* att = nullptr;
    cudaGetSymbolAddress((void**)&qkv, g_qkv);
    cudaGetSymbolAddress((void**)&att, g_att);

    const int M = BB * NN;   // 4096

    cudaFuncSetAttribute(gemm_mma_tf32,
                         cudaFuncAttributeMaxDynamicSharedMemorySize, GM_SMEM_BYTES);

    // Stage 1: QKV projection [4096,1024] x [3072,1024]^T -> [4096,3072]
    {
        dim3 grid(QKVW / 128, M / 128);
        gemm_mma_tf32<<<grid, 256, GM_SMEM_BYTES>>>(x, W_w, W_b, qkv, M, QKVW, DD);
    }

    // Stage 2: attention
    {
        const int smem = ATT_SMEM_FLOATS * (int)sizeof(float);
        cudaFuncSetAttribute(attn_kernel,
                             cudaFuncAttributeMaxDynamicSharedMemorySize, smem);
        dim3 grid(NN / 64, BB * HH);
        attn_kernel<<<grid, 256, smem>>>(qkv, att);
    }

    // Stage 3: output projection [4096,1024] x [1024,1024]^T -> [4096,1024]
    {
        dim3 grid(DD / 128, M / 128);
        gemm_mma_tf32<<<grid, 256, GM_SMEM_BYTES>>>(att, out_w, out_b, out, M, DD, DD);
    }
}

// round 6
// speedup vs baseline: 1.0026x; 1.0026x over previous
#include <cuda_runtime.h>
#include <math.h>
#include <stdint.h>

// Problem constants
#define BB 2
#define NN 2048
#define DD 1024
#define HH 16
#define DHD 64
#define QKVW (3 * HH * DHD)   // 3072

// Scratch buffers (device globals: allocation-free rule)
__device__ float g_qkv[BB * NN * QKVW];     // [B, N, 3072]  Q|K|V packed
__device__ float g_att[BB * NN * HH * DHD]; // [B, N, 1024]  attention output

// ============================================================================
// Helpers (sm_100 baseline ISA: mma.sync tf32 + cp.async; NO tcgen05/TMA)
// ============================================================================
__device__ __forceinline__ uint32_t smem_u32(const void* p) {
    uint32_t a;
    asm("{ .reg .u64 t; cvta.to.shared.u64 t, %1; cvt.u32.u64 %0, t; }"
        : "=r"(a) : "l"(p));
    return a;
}

__device__ __forceinline__ uint32_t f2tf(float x) {
    uint32_t r;
    asm("cvt.rna.tf32.f32 %0, %1;" : "=r"(r) : "f"(x));
    return r;
}

__device__ __forceinline__ void cp_async16(uint32_t saddr, const void* gptr) {
    asm volatile("cp.async.cg.shared.global [%0], [%1], 16;"
                 :: "r"(saddr), "l"(gptr));
}
#define CP_COMMIT() asm volatile("cp.async.commit_group;" ::: "memory")
#define CP_WAIT(n)  asm volatile("cp.async.wait_group %0;" :: "n"(n) : "memory")

// D += A(16x8, tf32, row) * B(8x8, tf32, col)
__device__ __forceinline__ void mma16n8k8(float* d, const uint32_t* a, const uint32_t* b) {
    asm volatile(
        "mma.sync.aligned.m16n8k8.row.col.f32.tf32.tf32.f32 "
        "{%0,%1,%2,%3}, {%4,%5,%6,%7}, {%8,%9}, {%0,%1,%2,%3};"
        : "+f"(d[0]), "+f"(d[1]), "+f"(d[2]), "+f"(d[3])
        : "r"(a[0]), "r"(a[1]), "r"(a[2]), "r"(a[3]), "r"(b[0]), "r"(b[1]));
}

// ============================================================================
// tf32 mma.sync GEMM (NT): C[m,n] = sum_k A[m,k] * W[n,k] + bias[n]
// CTA tile 128x128, BK=32, 256 threads (8 warps, 2x4), warp tile 64x32.
// SMEM: [row][k] at pitch 36 floats (conflict-free fragment LDS), double-buffered.
// ============================================================================
#define PITCH 36
#define BUF_FLOATS (128 * PITCH)                 // 4608 floats per matrix buffer
#define GM_SMEM_BYTES (4 * BUF_FLOATS * 4)       // A0,B0,A1,B1 = 73728 B

__global__ __launch_bounds__(256, 2)
void gemm_mma_tf32(const float* __restrict__ A,
                   const float* __restrict__ W,
                   const float* __restrict__ bias,
                   float* __restrict__ C,
                   int M, int Nc, int K)
{
    extern __shared__ float sm[];
    float* const Abuf[2] = { sm,                 sm + 2 * BUF_FLOATS };
    float* const Bbuf[2] = { sm + BUF_FLOATS,    sm + 3 * BUF_FLOATS };

    const int tid = threadIdx.x;
    const int wid = tid >> 5;
    const int lane = tid & 31;
    const int wm = wid & 1;          // 0..1 -> 64-row half
    const int wn = wid >> 1;         // 0..3 -> 32-col quarter
    const int g  = lane >> 2;        // groupID 0..7
    const int tg = lane & 3;         // thread-in-group 0..3
    const int m0 = blockIdx.y * 128;
    const int n0 = blockIdx.x * 128;

    const int r_cp  = tid >> 3;          // 0..31 base row for copies
    const int c4_cp = (tid & 7) * 4;     // 0,4,...,28

    float d[4][4][4];
#pragma unroll
    for (int i = 0; i < 4; ++i)
#pragma unroll
        for (int j = 0; j < 4; ++j)
#pragma unroll
            for (int r = 0; r < 4; ++r) d[i][j][r] = 0.f;

    const int nch = K >> 5;   // chunks of 32

    // --- issue copy of chunk kc into buffer buf ---
    auto issue_copy = [&](int buf, int kc) {
        const float* Ag = A + (size_t)m0 * K + kc * 32;
        const float* Wg = W + (size_t)n0 * K + kc * 32;
        float* as = Abuf[buf];
        float* bs = Bbuf[buf];
#pragma unroll
        for (int s = 0; s < 4; ++s) {
            int r = r_cp + s * 32;
            cp_async16(smem_u32(as + r * PITCH + c4_cp), Ag + (size_t)r * K + c4_cp);
            cp_async16(smem_u32(bs + r * PITCH + c4_cp), Wg + (size_t)r * K + c4_cp);
        }
        CP_COMMIT();
    };

    issue_copy(0, 0);

    for (int kc = 0; kc < nch; ++kc) {
        const int buf = kc & 1;
        if (kc + 1 < nch) {
            issue_copy(buf ^ 1, kc + 1);
            CP_WAIT(1);
        } else {
            CP_WAIT(0);
        }
        __syncthreads();

        const float* as = Abuf[buf];
        const float* bs = Bbuf[buf];

#pragma unroll
        for (int ks = 0; ks < 4; ++ks) {
            const int kb = ks * 8;
            uint32_t afr[4][4], bfr[4][2];
#pragma unroll
            for (int i = 0; i < 4; ++i) {
                const float* ap = as + (wm * 64 + i * 16 + g) * PITCH + kb + tg;
                afr[i][0] = f2tf(ap[0]);
                afr[i][1] = f2tf(ap[8 * PITCH]);
                afr[i][2] = f2tf(ap[4]);
                afr[i][3] = f2tf(ap[8 * PITCH + 4]);
            }
#pragma unroll
            for (int j = 0; j < 4; ++j) {
                const float* bp = bs + (wn * 32 + j * 8 + g) * PITCH + kb + tg;
                bfr[j][0] = f2tf(bp[0]);
                bfr[j][1] = f2tf(bp[4]);
            }
#pragma unroll
            for (int i = 0; i < 4; ++i)
#pragma unroll
                for (int j = 0; j < 4; ++j)
                    mma16n8k8(d[i][j], afr[i], bfr[j]);
        }
        __syncthreads();
    }

    // Epilogue: bias + store (float2 per fragment row)
#pragma unroll
    for (int j = 0; j < 4; ++j) {
        const int ncol = n0 + wn * 32 + j * 8 + 2 * tg;
        const float bv0 = bias[ncol];
        const float bv1 = bias[ncol + 1];
#pragma unroll
        for (int i = 0; i < 4; ++i) {
            const int mrow = m0 + wm * 64 + i * 16 + g;
            float2 v0 = { d[i][j][0] + bv0, d[i][j][1] + bv1 };
            float2 v1 = { d[i][j][2] + bv0, d[i][j][3] + bv1 };
            *(float2*)(C + (size_t)mrow * Nc + ncol) = v0;
            *(float2*)(C + (size_t)(mrow + 8) * Nc + ncol) = v1;
        }
    }
}

// ----------------------------------------------------------------------------
// Flash-style attention (fp32) — unchanged (passed R1).
// ----------------------------------------------------------------------------
#define ATT_PITCH 65
#define ATT_SMEM_FLOATS (3 * 64 * ATT_PITCH + 3 * 64)

__global__ __launch_bounds__(256)
void attn_kernel(const float* __restrict__ qkv, float* __restrict__ out)
{
    extern __shared__ float sma[];
    float* Qs   = sma;
    float* Ks   = Qs + 64 * ATT_PITCH;
    float* Vs   = Ks + 64 * ATT_PITCH;
    float* mrow = Vs + 64 * ATT_PITCH;
    float* lrow = mrow + 64;
    float* arow = lrow + 64;

    const int tid = threadIdx.x;
    const int tx = tid & 15;
    const int ty = tid >> 4;
    const int bh = blockIdx.y;
    const int b = bh >> 4;
    const int h = bh & 15;
    const int q0 = blockIdx.x * 64;

    const size_t rs = QKVW;
    const float* Qg = qkv + (size_t)(b * NN + q0) * rs + h * DHD;
    const float* Kg = qkv + (size_t)(b * NN) * rs + HH * DHD + h * DHD;
    const float* Vg = qkv + (size_t)(b * NN) * rs + 2 * HH * DHD + h * DHD;
    const float scale = 0.125f;

#pragma unroll
    for (int s = 0; s < 4; ++s) {
        int i = tid + s * 256;
        int r = i >> 4;
        int c = (i & 15) * 4;
        float4 v = *(const float4*)(Qg + (size_t)r * rs + c);
        Qs[r * ATT_PITCH + c + 0] = v.x * scale;
        Qs[r * ATT_PITCH + c + 1] = v.y * scale;
        Qs[r * ATT_PITCH + c + 2] = v.z * scale;
        Qs[r * ATT_PITCH + c + 3] = v.w * scale;
    }
    if (tid < 64) { mrow[tid] = -INFINITY; lrow[tid] = 0.f; }

    float Oacc[4][4];
#pragma unroll
    for (int i = 0; i < 4; ++i)
#pragma unroll
        for (int j = 0; j < 4; ++j) Oacc[i][j] = 0.f;

    __syncthreads();

    for (int j0 = 0; j0 < NN; j0 += 64) {
#pragma unroll
        for (int s = 0; s < 4; ++s) {
            int i = tid + s * 256;
            int r = i >> 4;
            int c = (i & 15) * 4;
            float4 kv = *(const float4*)(Kg + (size_t)(j0 + r) * rs + c);
            Ks[r * ATT_PITCH + c + 0] = kv.x;
            Ks[r * ATT_PITCH + c + 1] = kv.y;
            Ks[r * ATT_PITCH + c + 2] = kv.z;
            Ks[r * ATT_PITCH + c + 3] = kv.w;
            float4 vv = *(const float4*)(Vg + (size_t)(j0 + r) * rs + c);
            Vs[r * ATT_PITCH + c + 0] = vv.x;
            Vs[r * ATT_PITCH + c + 1] = vv.y;
            Vs[r * ATT_PITCH + c + 2] = vv.z;
            Vs[r * ATT_PITCH + c + 3] = vv.w;
        }
        __syncthreads();

        float Sa[4][4];
#pragma unroll
        for (int i = 0; i < 4; ++i)
#pragma unroll
            for (int j = 0; j < 4; ++j) Sa[i][j] = 0.f;

#pragma unroll
        for (int dd = 0; dd < 64; ++dd) {
            float qf[4], kf[4];
#pragma unroll
            for (int i = 0; i < 4; ++i) qf[i] = Qs[(ty * 4 + i) * ATT_PITCH + dd];
#pragma unroll
            for (int j = 0; j < 4; ++j) kf[j] = Ks[(tx * 4 + j) * ATT_PITCH + dd];
#pragma unroll
            for (int i = 0; i < 4; ++i)
#pragma unroll
                for (int j = 0; j < 4; ++j)
                    Sa[i][j] += qf[i] * kf[j];
        }
        __syncthreads();

#pragma unroll
        for (int i = 0; i < 4; ++i)
#pragma unroll
            for (int j = 0; j < 4; ++j)
                Ks[(ty * 4 + i) * ATT_PITCH + tx * 4 + j] = Sa[i][j];
        __syncthreads();

        {
            const int r = tid >> 2;
            const int seg = (tid & 3) * 16;
            float* Srow = Ks + r * ATT_PITCH + seg;
            float mx = -INFINITY;
#pragma unroll
            for (int j = 0; j < 16; ++j) mx = fmaxf(mx, Srow[j]);
            mx = fmaxf(mx, __shfl_xor_sync(0xffffffffu, mx, 1));
            mx = fmaxf(mx, __shfl_xor_sync(0xffffffffu, mx, 2));
            float mold = mrow[r];
            float mnew = fmaxf(mold, mx);
            float sum = 0.f;
#pragma unroll
            for (int j = 0; j < 16; ++j) {
                float e = __expf(Srow[j] - mnew);
                Srow[j] = e;
                sum += e;
            }
            sum += __shfl_xor_sync(0xffffffffu, sum, 1);
            sum += __shfl_xor_sync(0xffffffffu, sum, 2);
            if ((tid & 3) == 0) {
                float al = __expf(mold - mnew);
                arow[r] = al;
                lrow[r] = lrow[r] * al + sum;
                mrow[r] = mnew;
            }
        }
        __syncthreads();

        float al[4];
#pragma unroll
        for (int i = 0; i < 4; ++i) al[i] = arow[ty * 4 + i];
#pragma unroll
        for (int i = 0; i < 4; ++i)
#pragma unroll
            for (int j = 0; j < 4; ++j) Oacc[i][j] *= al[i];

#pragma unroll
        for (int k = 0; k < 64; ++k) {
            float pf[4], vf[4];
#pragma unroll
            for (int i = 0; i < 4; ++i) pf[i] = Ks[(ty * 4 + i) * ATT_PITCH + k];
#pragma unroll
            for (int j = 0; j < 4; ++j) vf[j] = Vs[k * ATT_PITCH + tx * 4 + j];
#pragma unroll
            for (int i = 0; i < 4; ++i)
#pragma unroll
                for (int j = 0; j < 4; ++j)
                    Oacc[i][j] += pf[i] * vf[j];
        }
        __syncthreads();
    }

#pragma unroll
    for (int i = 0; i < 4; ++i) {
        float inv = 1.f / lrow[ty * 4 + i];
        float4 o;
        o.x = Oacc[i][0] * inv;
        o.y = Oacc[i][1] * inv;
        o.z = Oacc[i][2] * inv;
        o.w = Oacc[i][3] * inv;
        float* op = out + (size_t)(b * NN + q0 + ty * 4 + i) * (HH * DHD)
                        + h * DHD + tx * 4;
        *(float4*)op = o;
    }
}

// ----------------------------------------------------------------------------
// Launch
// ----------------------------------------------------------------------------
extern "C" void kernel_launch(void* const* d_in, const int* in_sizes, int n_in,
                              void* d_out, int out_size)
{
    const float* x     = (const float*)d_in[0];
    const float* W_w   = (const float*)d_in[1];
    const float* W_b   = (const float*)d_in[2];
    const float* out_w = (const float*)d_in[3];
    const float* out_b = (const float*)d_in[4];
    float* out = (float*)d_out;

    float* qkv = nullptr;
    float* att = nullptr;
    cudaGetSymbolAddress((void**)&qkv, g_qkv);
    cudaGetSymbolAddress((void**)&att, g_att);

    const int M = BB * NN;   // 4096

    cudaFuncSetAttribute(gemm_mma_tf32,
                         cudaFuncAttributeMaxDynamicSharedMemorySize, GM_SMEM_BYTES);

    // Stage 1: QKV projection [4096,1024] x [3072,1024]^T -> [4096,3072]
    {
        dim3 grid(QKVW / 128, M / 128);
        gemm_mma_tf32<<<grid, 256, GM_SMEM_BYTES>>>(x, W_w, W_b, qkv, M, QKVW, DD);
    }

    // Stage 2: attention
    {
        const int smem = ATT_SMEM_FLOATS * (int)sizeof(float);
        cudaFuncSetAttribute(attn_kernel,
                             cudaFuncAttributeMaxDynamicSharedMemorySize, smem);
        dim3 grid(NN / 64, BB * HH);
        attn_kernel<<<grid, 256, smem>>>(qkv, att);
    }

    // Stage 3: output projection [4096,1024] x [1024,1024]^T -> [4096,1024]
    {
        dim3 grid(DD / 128, M / 128);
        gemm_mma_tf32<<<grid, 256, GM_SMEM_BYTES>>>(att, out_w, out_b, out, M, DD, DD);
    }
}